// round 2
// baseline (speedup 1.0000x reference)
#include <cuda_runtime.h>
#include <cuda_bf16.h>
#include <math.h>
#include <stdint.h>

// ContrastiveHead NT-Xent: loss = mean_i [10 + log(sum_{j!=i} e^{10 s_ij - 10}) - 10 s_{i,p(i)}]
// s = fn fn^T symmetric -> compute only upper-triangular 128x128 tile pairs,
// reuse each exp() for row- AND column-sums.

#define NROWS 8192
#define HALFN 4096
#define DIM   256
#define BM    128
#define KP    264
#define NTILE 64                       // 8192/128
#define NPAIRS (NTILE*(NTILE+1)/2)     // 2080
#define SMEM_TILES (2 * BM * KP * 2)   // two bf16 tiles
#define SMEM_BYTES (SMEM_TILES + 2 * BM * 4)

__device__ __nv_bfloat16 g_fbf[NROWS * DIM];
__device__ float g_pos[NROWS];
__device__ float g_sumexp[NROWS];

// ---------------------------------------------------------------------------
__global__ void normalize_kernel(const float* __restrict__ q,
                                 const float* __restrict__ k) {
    int gw   = (blockIdx.x * blockDim.x + threadIdx.x) >> 5;
    int lane = threadIdx.x & 31;
    if (gw >= NROWS) return;
    const float* src = (gw < HALFN) ? (q + (size_t)gw * DIM)
                                    : (k + (size_t)(gw - HALFN) * DIM);
    const float4* s4 = (const float4*)src;
    float4 v0 = s4[lane * 2 + 0];
    float4 v1 = s4[lane * 2 + 1];
    float ss = v0.x*v0.x + v0.y*v0.y + v0.z*v0.z + v0.w*v0.w
             + v1.x*v1.x + v1.y*v1.y + v1.z*v1.z + v1.w*v1.w;
    #pragma unroll
    for (int o = 16; o; o >>= 1) ss += __shfl_xor_sync(0xffffffffu, ss, o);
    float scale = 1.0f / fmaxf(sqrtf(ss), 1e-12f);

    __nv_bfloat162 h0 = __floats2bfloat162_rn(v0.x * scale, v0.y * scale);
    __nv_bfloat162 h1 = __floats2bfloat162_rn(v0.z * scale, v0.w * scale);
    __nv_bfloat162 h2 = __floats2bfloat162_rn(v1.x * scale, v1.y * scale);
    __nv_bfloat162 h3 = __floats2bfloat162_rn(v1.z * scale, v1.w * scale);
    uint4 o4;
    o4.x = *(const uint32_t*)&h0;
    o4.y = *(const uint32_t*)&h1;
    o4.z = *(const uint32_t*)&h2;
    o4.w = *(const uint32_t*)&h3;
    *(uint4*)(g_fbf + (size_t)gw * DIM + lane * 8) = o4;
}

// ---------------------------------------------------------------------------
// fp32-exact positives + zero accumulators + zero output scalar.
// ---------------------------------------------------------------------------
__global__ void pos_kernel(const float* __restrict__ q,
                           const float* __restrict__ k,
                           float* __restrict__ out) {
    int gt = blockIdx.x * blockDim.x + threadIdx.x;
    if (gt == 0) out[0] = 0.0f;
    if (gt < NROWS) g_sumexp[gt] = 0.0f;
    int gw   = gt >> 5;
    int lane = gt & 31;
    if (gw >= HALFN) return;
    const float4* q4 = (const float4*)(q + (size_t)gw * DIM);
    const float4* k4 = (const float4*)(k + (size_t)gw * DIM);
    float4 a0 = q4[lane*2], a1 = q4[lane*2+1];
    float4 b0 = k4[lane*2], b1 = k4[lane*2+1];
    float sq = a0.x*a0.x + a0.y*a0.y + a0.z*a0.z + a0.w*a0.w
             + a1.x*a1.x + a1.y*a1.y + a1.z*a1.z + a1.w*a1.w;
    float sk = b0.x*b0.x + b0.y*b0.y + b0.z*b0.z + b0.w*b0.w
             + b1.x*b1.x + b1.y*b1.y + b1.z*b1.z + b1.w*b1.w;
    float dp = a0.x*b0.x + a0.y*b0.y + a0.z*b0.z + a0.w*b0.w
             + a1.x*b1.x + a1.y*b1.y + a1.z*b1.z + a1.w*b1.w;
    #pragma unroll
    for (int o = 16; o; o >>= 1) {
        sq += __shfl_xor_sync(0xffffffffu, sq, o);
        sk += __shfl_xor_sync(0xffffffffu, sk, o);
        dp += __shfl_xor_sync(0xffffffffu, dp, o);
    }
    if (lane == 0) {
        float p = dp / (fmaxf(sqrtf(sq), 1e-12f) * fmaxf(sqrtf(sk), 1e-12f));
        g_pos[gw]         = p;
        g_pos[gw + HALFN] = p;
    }
}

// ---------------------------------------------------------------------------
__device__ __forceinline__ void ldsm_x4(uint32_t* r, const void* p) {
    uint32_t a = (uint32_t)__cvta_generic_to_shared(p);
    asm volatile("ldmatrix.sync.aligned.m8n8.x4.shared.b16 {%0,%1,%2,%3}, [%4];"
                 : "=r"(r[0]), "=r"(r[1]), "=r"(r[2]), "=r"(r[3]) : "r"(a));
}
__device__ __forceinline__ void ldsm_x2(uint32_t* r, const void* p) {
    uint32_t a = (uint32_t)__cvta_generic_to_shared(p);
    asm volatile("ldmatrix.sync.aligned.m8n8.x2.shared.b16 {%0,%1}, [%2];"
                 : "=r"(r[0]), "=r"(r[1]) : "r"(a));
}
__device__ __forceinline__ void mma16816(float* c, const uint32_t* a, const uint32_t* b) {
    asm volatile(
        "mma.sync.aligned.m16n8k16.row.col.f32.bf16.bf16.f32 "
        "{%0,%1,%2,%3}, {%4,%5,%6,%7}, {%8,%9}, {%0,%1,%2,%3};"
        : "+f"(c[0]), "+f"(c[1]), "+f"(c[2]), "+f"(c[3])
        : "r"(a[0]), "r"(a[1]), "r"(a[2]), "r"(a[3]), "r"(b[0]), "r"(b[1]));
}

// ---------------------------------------------------------------------------
// Symmetric fused GEMM+exp. One CTA per upper-triangular tile pair (bi<=bj).
// 256 threads = 8 warps, 4(m) x 2(n). Off-diag tiles feed both row sums (bi)
// and column sums (bj) from the same exp() values.
// ---------------------------------------------------------------------------
__global__ void __launch_bounds__(256, 1) sim_kernel() {
    extern __shared__ __nv_bfloat16 sm[];
    __nv_bfloat16* As = sm;
    __nv_bfloat16* Bs = sm + BM * KP;
    float* sh_row = (float*)(sm + 2 * BM * KP);
    float* sh_col = sh_row + BM;

    int tid = threadIdx.x;
    int lane = tid & 31;
    int w = tid >> 5;
    int wm = w >> 1;
    int wn = w & 1;

    // Linear triangular index -> (bi, bj), bj >= bi.
    int t = blockIdx.x;
    int bi = 0, rem = t;
    while (rem >= NTILE - bi) { rem -= NTILE - bi; ++bi; }
    int bj = bi + rem;
    bool diag = (bi == bj);

    if (tid < BM) { sh_row[tid] = 0.f; sh_col[tid] = 0.f; }

    for (int idx = tid; idx < BM * (DIM / 8); idx += 256) {
        int r = idx >> 5, c = idx & 31;
        uint4 v = ((const uint4*)(g_fbf + (size_t)(bi * BM + r) * DIM))[c];
        *(uint4*)(As + r * KP + c * 8) = v;
    }
    if (!diag) {
        for (int idx = tid; idx < BM * (DIM / 8); idx += 256) {
            int r = idx >> 5, c = idx & 31;
            uint4 v = ((const uint4*)(g_fbf + (size_t)(bj * BM + r) * DIM))[c];
            *(uint4*)(Bs + r * KP + c * 8) = v;
        }
    }
    const __nv_bfloat16* Bsel = diag ? As : Bs;
    __syncthreads();

    float cfr[2][8][4];
    #pragma unroll
    for (int mt = 0; mt < 2; ++mt)
        #pragma unroll
        for (int nt = 0; nt < 8; ++nt)
            #pragma unroll
            for (int e = 0; e < 4; ++e) cfr[mt][nt][e] = 0.f;

    int al = lane & 15;
    int acolo = (lane >> 4) * 8;
    int brow_off = lane & 7;
    int bcolo = ((lane >> 3) & 1) * 8;

    #pragma unroll 4
    for (int kk = 0; kk < 16; ++kk) {
        int k0 = kk * 16;
        uint32_t afr[2][4], bfr[8][2];
        #pragma unroll
        for (int mt = 0; mt < 2; ++mt)
            ldsm_x4(afr[mt], As + (wm * 32 + mt * 16 + al) * KP + k0 + acolo);
        #pragma unroll
        for (int nt = 0; nt < 8; ++nt)
            ldsm_x2(bfr[nt], Bsel + (wn * 64 + nt * 8 + brow_off) * KP + k0 + bcolo);
        #pragma unroll
        for (int mt = 0; mt < 2; ++mt)
            #pragma unroll
            for (int nt = 0; nt < 8; ++nt)
                mma16816(cfr[mt][nt], afr[mt], bfr[nt]);
    }

    // Epilogue: e = exp(10 s - 10), diag masked; row sums + column sums.
    int g  = lane >> 2;
    int qd = (lane & 3) * 2;
    const float C10 = 14.426950408889634f;   // 10 * log2(e)
    float rowsum[4] = {0.f, 0.f, 0.f, 0.f};
    float colsum[8][2];
    #pragma unroll
    for (int nt = 0; nt < 8; ++nt) { colsum[nt][0] = 0.f; colsum[nt][1] = 0.f; }

    #pragma unroll
    for (int mt = 0; mt < 2; ++mt) {
        int gr0 = bi * BM + wm * 32 + mt * 16 + g;    // and gr0 + 8
        #pragma unroll
        for (int nt = 0; nt < 8; ++nt) {
            int gc0 = bj * BM + wn * 64 + nt * 8 + qd;
            float* cc = cfr[mt][nt];
            float e0 = (gc0     != gr0    ) ? exp2f((cc[0] - 1.f) * C10) : 0.f;
            float e1 = (gc0 + 1 != gr0    ) ? exp2f((cc[1] - 1.f) * C10) : 0.f;
            float e2 = (gc0     != gr0 + 8) ? exp2f((cc[2] - 1.f) * C10) : 0.f;
            float e3 = (gc0 + 1 != gr0 + 8) ? exp2f((cc[3] - 1.f) * C10) : 0.f;
            rowsum[mt * 2 + 0] += e0 + e1;
            rowsum[mt * 2 + 1] += e2 + e3;
            colsum[nt][0] += e0 + e2;
            colsum[nt][1] += e1 + e3;
        }
    }

    // Row sums: reduce across the 4 lanes sharing a row.
    #pragma unroll
    for (int j = 0; j < 4; ++j) {
        rowsum[j] += __shfl_xor_sync(0xffffffffu, rowsum[j], 1);
        rowsum[j] += __shfl_xor_sync(0xffffffffu, rowsum[j], 2);
    }
    if ((lane & 3) == 0) {
        #pragma unroll
        for (int mt = 0; mt < 2; ++mt) {
            int r0 = wm * 32 + mt * 16 + g;
            atomicAdd(&sh_row[r0],     rowsum[mt * 2 + 0]);
            atomicAdd(&sh_row[r0 + 8], rowsum[mt * 2 + 1]);
        }
    }

    // Column sums (off-diagonal tiles only): reduce across the 8 row-groups.
    if (!diag) {
        #pragma unroll
        for (int nt = 0; nt < 8; ++nt) {
            float c0 = colsum[nt][0], c1 = colsum[nt][1];
            #pragma unroll
            for (int o = 4; o <= 16; o <<= 1) {
                c0 += __shfl_xor_sync(0xffffffffu, c0, o);
                c1 += __shfl_xor_sync(0xffffffffu, c1, o);
            }
            if (lane < 4) {
                int col = wn * 64 + nt * 8 + lane * 2;
                atomicAdd(&sh_col[col],     c0);
                atomicAdd(&sh_col[col + 1], c1);
            }
        }
    }
    __syncthreads();

    if (tid < BM) {
        atomicAdd(&g_sumexp[bi * BM + tid], sh_row[tid]);
        if (!diag) atomicAdd(&g_sumexp[bj * BM + tid], sh_col[tid]);
    }
}

// ---------------------------------------------------------------------------
// Parallel finalize: 8192 threads, warp-reduce, atomic into out[0] (pre-zeroed).
// ---------------------------------------------------------------------------
__global__ void finalize_kernel(float* __restrict__ out) {
    int i = blockIdx.x * blockDim.x + threadIdx.x;
    float v = (10.f + logf(g_sumexp[i]) - 10.f * g_pos[i]) * (1.0f / (float)NROWS);
    #pragma unroll
    for (int o = 16; o; o >>= 1) v += __shfl_xor_sync(0xffffffffu, v, o);
    if ((threadIdx.x & 31) == 0) atomicAdd(out, v);
}

extern "C" void kernel_launch(void* const* d_in, const int* in_sizes, int n_in,
                              void* d_out, int out_size) {
    const float* q = (const float*)d_in[0];
    const float* k = (const float*)d_in[1];
    float* out = (float*)d_out;

    cudaFuncSetAttribute(sim_kernel, cudaFuncAttributeMaxDynamicSharedMemorySize,
                         SMEM_BYTES);

    normalize_kernel<<<NROWS / 8, 256>>>(q, k);
    pos_kernel<<<HALFN / 8, 256>>>(q, k, out);
    sim_kernel<<<NPAIRS, 256, SMEM_BYTES>>>();
    finalize_kernel<<<NROWS / 512, 512>>>(out);
}

// round 3
// speedup vs baseline: 1.8404x; 1.8404x over previous
#include <cuda_runtime.h>
#include <cuda_bf16.h>
#include <math.h>
#include <stdint.h>

// ContrastiveHead NT-Xent. Symmetric sim matrix: enumerate only upper-triangular
// 128x128 tiles. CTA = (row panel bi, chunk of <=8 bj tiles). A resident in smem,
// B double-buffered via cp.async. Row sums in registers, col sums via global atomics.

#define NROWS 8192
#define HALFN 4096
#define DIM   256
#define BM    128
#define KP    264                       // padded bf16 row stride (528 B)
#define NTILE 64
#define TSLICE 8
#define NCTAS 288                       // sum_bi ceil((64-bi)/8)
#define SMEM_BYTES (3 * BM * KP * 2)    // A + 2x B buffers

__device__ __nv_bfloat16 g_fbf[NROWS * DIM];
__device__ float g_pos[NROWS];
__device__ float g_sumexp[NROWS];

// ---------------------------------------------------------------------------
__global__ void normalize_kernel(const float* __restrict__ q,
                                 const float* __restrict__ k) {
    int gw   = (blockIdx.x * blockDim.x + threadIdx.x) >> 5;
    int lane = threadIdx.x & 31;
    if (gw >= NROWS) return;
    const float* src = (gw < HALFN) ? (q + (size_t)gw * DIM)
                                    : (k + (size_t)(gw - HALFN) * DIM);
    const float4* s4 = (const float4*)src;
    float4 v0 = s4[lane * 2 + 0];
    float4 v1 = s4[lane * 2 + 1];
    float ss = v0.x*v0.x + v0.y*v0.y + v0.z*v0.z + v0.w*v0.w
             + v1.x*v1.x + v1.y*v1.y + v1.z*v1.z + v1.w*v1.w;
    #pragma unroll
    for (int o = 16; o; o >>= 1) ss += __shfl_xor_sync(0xffffffffu, ss, o);
    float scale = 1.0f / fmaxf(sqrtf(ss), 1e-12f);

    __nv_bfloat162 h0 = __floats2bfloat162_rn(v0.x * scale, v0.y * scale);
    __nv_bfloat162 h1 = __floats2bfloat162_rn(v0.z * scale, v0.w * scale);
    __nv_bfloat162 h2 = __floats2bfloat162_rn(v1.x * scale, v1.y * scale);
    __nv_bfloat162 h3 = __floats2bfloat162_rn(v1.z * scale, v1.w * scale);
    uint4 o4;
    o4.x = *(const uint32_t*)&h0;
    o4.y = *(const uint32_t*)&h1;
    o4.z = *(const uint32_t*)&h2;
    o4.w = *(const uint32_t*)&h3;
    *(uint4*)(g_fbf + (size_t)gw * DIM + lane * 8) = o4;
}

// ---------------------------------------------------------------------------
__global__ void pos_kernel(const float* __restrict__ q,
                           const float* __restrict__ k,
                           float* __restrict__ out) {
    int gt = blockIdx.x * blockDim.x + threadIdx.x;
    if (gt == 0) out[0] = 0.0f;
    if (gt < NROWS) g_sumexp[gt] = 0.0f;
    int gw   = gt >> 5;
    int lane = gt & 31;
    if (gw >= HALFN) return;
    const float4* q4 = (const float4*)(q + (size_t)gw * DIM);
    const float4* k4 = (const float4*)(k + (size_t)gw * DIM);
    float4 a0 = q4[lane*2], a1 = q4[lane*2+1];
    float4 b0 = k4[lane*2], b1 = k4[lane*2+1];
    float sq = a0.x*a0.x + a0.y*a0.y + a0.z*a0.z + a0.w*a0.w
             + a1.x*a1.x + a1.y*a1.y + a1.z*a1.z + a1.w*a1.w;
    float sk = b0.x*b0.x + b0.y*b0.y + b0.z*b0.z + b0.w*b0.w
             + b1.x*b1.x + b1.y*b1.y + b1.z*b1.z + b1.w*b1.w;
    float dp = a0.x*b0.x + a0.y*b0.y + a0.z*b0.z + a0.w*b0.w
             + a1.x*b1.x + a1.y*b1.y + a1.z*b1.z + a1.w*b1.w;
    #pragma unroll
    for (int o = 16; o; o >>= 1) {
        sq += __shfl_xor_sync(0xffffffffu, sq, o);
        sk += __shfl_xor_sync(0xffffffffu, sk, o);
        dp += __shfl_xor_sync(0xffffffffu, dp, o);
    }
    if (lane == 0) {
        float p = dp / (fmaxf(sqrtf(sq), 1e-12f) * fmaxf(sqrtf(sk), 1e-12f));
        g_pos[gw]         = p;
        g_pos[gw + HALFN] = p;
    }
}

// ---------------------------------------------------------------------------
__device__ __forceinline__ void ldsm_x4(uint32_t* r, const void* p) {
    uint32_t a = (uint32_t)__cvta_generic_to_shared(p);
    asm volatile("ldmatrix.sync.aligned.m8n8.x4.shared.b16 {%0,%1,%2,%3}, [%4];"
                 : "=r"(r[0]), "=r"(r[1]), "=r"(r[2]), "=r"(r[3]) : "r"(a));
}
__device__ __forceinline__ void ldsm_x2(uint32_t* r, const void* p) {
    uint32_t a = (uint32_t)__cvta_generic_to_shared(p);
    asm volatile("ldmatrix.sync.aligned.m8n8.x2.shared.b16 {%0,%1}, [%2];"
                 : "=r"(r[0]), "=r"(r[1]) : "r"(a));
}
__device__ __forceinline__ void mma16816(float* c, const uint32_t* a, const uint32_t* b) {
    asm volatile(
        "mma.sync.aligned.m16n8k16.row.col.f32.bf16.bf16.f32 "
        "{%0,%1,%2,%3}, {%4,%5,%6,%7}, {%8,%9}, {%0,%1,%2,%3};"
        : "+f"(c[0]), "+f"(c[1]), "+f"(c[2]), "+f"(c[3])
        : "r"(a[0]), "r"(a[1]), "r"(a[2]), "r"(a[3]), "r"(b[0]), "r"(b[1]));
}
__device__ __forceinline__ void cp16(void* smem_dst, const void* gsrc) {
    uint32_t d = (uint32_t)__cvta_generic_to_shared(smem_dst);
    asm volatile("cp.async.cg.shared.global [%0], [%1], 16;" :: "r"(d), "l"(gsrc));
}
__device__ __forceinline__ void cp_commit() {
    asm volatile("cp.async.commit_group;");
}
__device__ __forceinline__ void cp_wait0() {
    asm volatile("cp.async.wait_group 0;");
}

// ---------------------------------------------------------------------------
// Fused symmetric GEMM + exp. 256 threads = 8 warps (4m x 2n).
// ---------------------------------------------------------------------------
__global__ void __launch_bounds__(256, 1) sim_kernel() {
    extern __shared__ __nv_bfloat16 sm[];
    __nv_bfloat16* As = sm;
    __nv_bfloat16* Bbuf[2] = { sm + BM * KP, sm + 2 * BM * KP };

    int tid = threadIdx.x;
    int lane = tid & 31;
    int w = tid >> 5;
    int wm = w >> 1;
    int wn = w & 1;

    // blockIdx -> (bi, bj0): row panel + start of column-tile chunk.
    int rem = blockIdx.x;
    int bi = 0;
    for (;;) {
        int s = (NTILE - bi + TSLICE - 1) / TSLICE;
        if (rem < s) break;
        rem -= s; ++bi;
    }
    int bj0 = bi + rem * TSLICE;
    int ntl = NTILE - bj0; if (ntl > TSLICE) ntl = TSLICE;

    // Async-load A panel + first B tile (one group).
    {
        int r = tid >> 1, c = (tid & 1) * 16;     // 2 threads/row, 16x16B... no:
    }
    // 128 rows x 512B per tile = 4096 x16B chunks; 16 per thread.
    for (int i = 0; i < 16; ++i) {
        int idx = tid + i * 256;                  // 0..4095
        int r = idx >> 5, c = idx & 31;           // row, 16B-chunk
        cp16(As + r * KP + c * 8, g_fbf + (size_t)(bi * BM + r) * DIM + c * 8);
    }
    for (int i = 0; i < 16; ++i) {
        int idx = tid + i * 256;
        int r = idx >> 5, c = idx & 31;
        cp16(Bbuf[0] + r * KP + c * 8, g_fbf + (size_t)(bj0 * BM + r) * DIM + c * 8);
    }
    cp_commit();

    int al = lane & 15;
    int acolo = (lane >> 4) * 8;
    int brow_off = lane & 7;
    int bcolo = ((lane >> 3) & 1) * 8;
    int g  = lane >> 2;
    int qd = (lane & 3) * 2;
    const float C10 = 14.426950408889634f;        // 10 * log2(e)

    float rowsum[4] = {0.f, 0.f, 0.f, 0.f};

    for (int t = 0; t < ntl; ++t) {
        cp_wait0();
        __syncthreads();                           // tile t visible; tile t-1 reads done

        if (t + 1 < ntl) {
            __nv_bfloat16* nb = Bbuf[(t + 1) & 1];
            const __nv_bfloat16* gsrc = g_fbf + (size_t)((bj0 + t + 1) * BM) * DIM;
            #pragma unroll
            for (int i = 0; i < 16; ++i) {
                int idx = tid + i * 256;
                int r = idx >> 5, c = idx & 31;
                cp16(nb + r * KP + c * 8, gsrc + (size_t)r * DIM + c * 8);
            }
        }
        cp_commit();                               // commit even if empty (keeps wait0 cheap)

        const __nv_bfloat16* Bs = Bbuf[t & 1];
        int bj = bj0 + t;
        bool diag = (bj == bi);

        float cfr[2][8][4];
        #pragma unroll
        for (int mt = 0; mt < 2; ++mt)
            #pragma unroll
            for (int nt = 0; nt < 8; ++nt)
                #pragma unroll
                for (int e = 0; e < 4; ++e) cfr[mt][nt][e] = 0.f;

        #pragma unroll 4
        for (int kk = 0; kk < 16; ++kk) {
            int k0 = kk * 16;
            uint32_t afr[2][4], bfr[8][2];
            #pragma unroll
            for (int mt = 0; mt < 2; ++mt)
                ldsm_x4(afr[mt], As + (wm * 32 + mt * 16 + al) * KP + k0 + acolo);
            #pragma unroll
            for (int nt = 0; nt < 8; ++nt)
                ldsm_x2(bfr[nt], Bs + (wn * 64 + nt * 8 + brow_off) * KP + k0 + bcolo);
            #pragma unroll
            for (int mt = 0; mt < 2; ++mt)
                #pragma unroll
                for (int nt = 0; nt < 8; ++nt)
                    mma16816(cfr[mt][nt], afr[mt], bfr[nt]);
        }

        // Epilogue: e = exp(10 s - 10); diag elements masked; accumulate rows
        // (registers, across slice) and columns (shuffle + global atomics).
        float colsum[8][2];
        #pragma unroll
        for (int nt = 0; nt < 8; ++nt) { colsum[nt][0] = 0.f; colsum[nt][1] = 0.f; }

        #pragma unroll
        for (int mt = 0; mt < 2; ++mt) {
            int gr0 = bi * BM + wm * 32 + mt * 16 + g;
            #pragma unroll
            for (int nt = 0; nt < 8; ++nt) {
                int gc0 = bj * BM + wn * 64 + nt * 8 + qd;
                float* cc = cfr[mt][nt];
                float e0 = (gc0     != gr0    ) ? exp2f((cc[0] - 1.f) * C10) : 0.f;
                float e1 = (gc0 + 1 != gr0    ) ? exp2f((cc[1] - 1.f) * C10) : 0.f;
                float e2 = (gc0     != gr0 + 8) ? exp2f((cc[2] - 1.f) * C10) : 0.f;
                float e3 = (gc0 + 1 != gr0 + 8) ? exp2f((cc[3] - 1.f) * C10) : 0.f;
                rowsum[mt * 2 + 0] += e0 + e1;
                rowsum[mt * 2 + 1] += e2 + e3;
                colsum[nt][0] += e0 + e2;
                colsum[nt][1] += e1 + e3;
            }
        }

        if (!diag) {
            #pragma unroll
            for (int nt = 0; nt < 8; ++nt) {
                float c0 = colsum[nt][0], c1 = colsum[nt][1];
                #pragma unroll
                for (int o = 4; o <= 16; o <<= 1) {
                    c0 += __shfl_xor_sync(0xffffffffu, c0, o);
                    c1 += __shfl_xor_sync(0xffffffffu, c1, o);
                }
                if (lane < 4) {
                    int col = bj * BM + wn * 64 + nt * 8 + lane * 2;
                    atomicAdd(&g_sumexp[col],     c0);
                    atomicAdd(&g_sumexp[col + 1], c1);
                }
            }
        }
    }

    // Flush row sums (accumulated over whole slice).
    #pragma unroll
    for (int j = 0; j < 4; ++j) {
        rowsum[j] += __shfl_xor_sync(0xffffffffu, rowsum[j], 1);
        rowsum[j] += __shfl_xor_sync(0xffffffffu, rowsum[j], 2);
    }
    if ((lane & 3) == 0) {
        #pragma unroll
        for (int mt = 0; mt < 2; ++mt) {
            int r0 = bi * BM + wm * 32 + mt * 16 + g;
            atomicAdd(&g_sumexp[r0],     rowsum[mt * 2 + 0]);
            atomicAdd(&g_sumexp[r0 + 8], rowsum[mt * 2 + 1]);
        }
    }
}

// ---------------------------------------------------------------------------
__global__ void finalize_kernel(float* __restrict__ out) {
    int i = blockIdx.x * blockDim.x + threadIdx.x;
    float v = (10.f + __logf(g_sumexp[i]) - 10.f * g_pos[i]) * (1.0f / (float)NROWS);
    #pragma unroll
    for (int o = 16; o; o >>= 1) v += __shfl_xor_sync(0xffffffffu, v, o);
    if ((threadIdx.x & 31) == 0) atomicAdd(out, v);
}

extern "C" void kernel_launch(void* const* d_in, const int* in_sizes, int n_in,
                              void* d_out, int out_size) {
    const float* q = (const float*)d_in[0];
    const float* k = (const float*)d_in[1];
    float* out = (float*)d_out;

    cudaFuncSetAttribute(sim_kernel, cudaFuncAttributeMaxDynamicSharedMemorySize,
                         SMEM_BYTES);

    normalize_kernel<<<NROWS / 8, 256>>>(q, k);
    pos_kernel<<<HALFN / 8, 256>>>(q, k, out);
    sim_kernel<<<NCTAS, 256, SMEM_BYTES>>>();
    finalize_kernel<<<NROWS / 512, 512>>>(out);
}

// round 4
// speedup vs baseline: 2.2419x; 1.2182x over previous
#include <cuda_runtime.h>
#include <cuda_bf16.h>
#include <math.h>
#include <stdint.h>

// ContrastiveHead NT-Xent. Symmetric sim: upper-triangular 128x128 tiles.
// CTA = (row panel bi, <=8 bj tiles). 512 threads (16 warps, 4m x 4n).
// A resident, B double-buffered cp.async. Row sums in regs, col sums atomics.

#define NROWS 8192
#define HALFN 4096
#define DIM   256
#define BM    128
#define KP    264
#define NTILE 64
#define TSLICE 8
#define NCTAS 288
#define NTHREADS 512
#define SMEM_BYTES (3 * BM * KP * 2)

__device__ __nv_bfloat16 g_fbf[NROWS * DIM];
__device__ float g_pos[NROWS];
__device__ float g_sumexp[NROWS];

// ---------------------------------------------------------------------------
__global__ void normalize_kernel(const float* __restrict__ q,
                                 const float* __restrict__ k) {
    int gw   = (blockIdx.x * blockDim.x + threadIdx.x) >> 5;
    int lane = threadIdx.x & 31;
    if (gw >= NROWS) return;
    const float* src = (gw < HALFN) ? (q + (size_t)gw * DIM)
                                    : (k + (size_t)(gw - HALFN) * DIM);
    const float4* s4 = (const float4*)src;
    float4 v0 = s4[lane * 2 + 0];
    float4 v1 = s4[lane * 2 + 1];
    float ss = v0.x*v0.x + v0.y*v0.y + v0.z*v0.z + v0.w*v0.w
             + v1.x*v1.x + v1.y*v1.y + v1.z*v1.z + v1.w*v1.w;
    #pragma unroll
    for (int o = 16; o; o >>= 1) ss += __shfl_xor_sync(0xffffffffu, ss, o);
    float scale = 1.0f / fmaxf(sqrtf(ss), 1e-12f);

    __nv_bfloat162 h0 = __floats2bfloat162_rn(v0.x * scale, v0.y * scale);
    __nv_bfloat162 h1 = __floats2bfloat162_rn(v0.z * scale, v0.w * scale);
    __nv_bfloat162 h2 = __floats2bfloat162_rn(v1.x * scale, v1.y * scale);
    __nv_bfloat162 h3 = __floats2bfloat162_rn(v1.z * scale, v1.w * scale);
    uint4 o4;
    o4.x = *(const uint32_t*)&h0;
    o4.y = *(const uint32_t*)&h1;
    o4.z = *(const uint32_t*)&h2;
    o4.w = *(const uint32_t*)&h3;
    *(uint4*)(g_fbf + (size_t)gw * DIM + lane * 8) = o4;
}

// ---------------------------------------------------------------------------
__global__ void pos_kernel(const float* __restrict__ q,
                           const float* __restrict__ k,
                           float* __restrict__ out) {
    int gt = blockIdx.x * blockDim.x + threadIdx.x;
    if (gt == 0) out[0] = 0.0f;
    if (gt < NROWS) g_sumexp[gt] = 0.0f;
    int gw   = gt >> 5;
    int lane = gt & 31;
    if (gw >= HALFN) return;
    const float4* q4 = (const float4*)(q + (size_t)gw * DIM);
    const float4* k4 = (const float4*)(k + (size_t)gw * DIM);
    float4 a0 = q4[lane*2], a1 = q4[lane*2+1];
    float4 b0 = k4[lane*2], b1 = k4[lane*2+1];
    float sq = a0.x*a0.x + a0.y*a0.y + a0.z*a0.z + a0.w*a0.w
             + a1.x*a1.x + a1.y*a1.y + a1.z*a1.z + a1.w*a1.w;
    float sk = b0.x*b0.x + b0.y*b0.y + b0.z*b0.z + b0.w*b0.w
             + b1.x*b1.x + b1.y*b1.y + b1.z*b1.z + b1.w*b1.w;
    float dp = a0.x*b0.x + a0.y*b0.y + a0.z*b0.z + a0.w*b0.w
             + a1.x*b1.x + a1.y*b1.y + a1.z*b1.z + a1.w*b1.w;
    #pragma unroll
    for (int o = 16; o; o >>= 1) {
        sq += __shfl_xor_sync(0xffffffffu, sq, o);
        sk += __shfl_xor_sync(0xffffffffu, sk, o);
        dp += __shfl_xor_sync(0xffffffffu, dp, o);
    }
    if (lane == 0) {
        float p = dp / (fmaxf(sqrtf(sq), 1e-12f) * fmaxf(sqrtf(sk), 1e-12f));
        g_pos[gw]         = p;
        g_pos[gw + HALFN] = p;
    }
}

// ---------------------------------------------------------------------------
__device__ __forceinline__ void ldsm_x4(uint32_t* r, const void* p) {
    uint32_t a = (uint32_t)__cvta_generic_to_shared(p);
    asm volatile("ldmatrix.sync.aligned.m8n8.x4.shared.b16 {%0,%1,%2,%3}, [%4];"
                 : "=r"(r[0]), "=r"(r[1]), "=r"(r[2]), "=r"(r[3]) : "r"(a));
}
__device__ __forceinline__ void ldsm_x2(uint32_t* r, const void* p) {
    uint32_t a = (uint32_t)__cvta_generic_to_shared(p);
    asm volatile("ldmatrix.sync.aligned.m8n8.x2.shared.b16 {%0,%1}, [%2];"
                 : "=r"(r[0]), "=r"(r[1]) : "r"(a));
}
__device__ __forceinline__ void mma16816(float* c, const uint32_t* a, const uint32_t* b) {
    asm volatile(
        "mma.sync.aligned.m16n8k16.row.col.f32.bf16.bf16.f32 "
        "{%0,%1,%2,%3}, {%4,%5,%6,%7}, {%8,%9}, {%0,%1,%2,%3};"
        : "+f"(c[0]), "+f"(c[1]), "+f"(c[2]), "+f"(c[3])
        : "r"(a[0]), "r"(a[1]), "r"(a[2]), "r"(a[3]), "r"(b[0]), "r"(b[1]));
}
__device__ __forceinline__ float ex2(float x) {
    float y;
    asm("ex2.approx.ftz.f32 %0, %1;" : "=f"(y) : "f"(x));
    return y;
}
__device__ __forceinline__ void cp16(void* smem_dst, const void* gsrc) {
    uint32_t d = (uint32_t)__cvta_generic_to_shared(smem_dst);
    asm volatile("cp.async.cg.shared.global [%0], [%1], 16;" :: "r"(d), "l"(gsrc));
}
__device__ __forceinline__ void cp_commit() { asm volatile("cp.async.commit_group;"); }
__device__ __forceinline__ void cp_wait0()  { asm volatile("cp.async.wait_group 0;"); }

// ---------------------------------------------------------------------------
// Fused symmetric GEMM + exp. 512 threads = 16 warps (4m x 4n).
// Per warp: 2 m-tiles (m16) x 4 n-tiles (n8).
// ---------------------------------------------------------------------------
__global__ void __launch_bounds__(NTHREADS, 1) sim_kernel() {
    extern __shared__ __nv_bfloat16 sm[];
    __nv_bfloat16* As = sm;
    __nv_bfloat16* Bbuf[2] = { sm + BM * KP, sm + 2 * BM * KP };

    int tid = threadIdx.x;
    int lane = tid & 31;
    int w = tid >> 5;
    int wm = w >> 2;            // 0..3
    int wn = w & 3;             // 0..3

    int rem = blockIdx.x;
    int bi = 0;
    for (;;) {
        int s = (NTILE - bi + TSLICE - 1) / TSLICE;
        if (rem < s) break;
        rem -= s; ++bi;
    }
    int bj0 = bi + rem * TSLICE;
    int ntl = NTILE - bj0; if (ntl > TSLICE) ntl = TSLICE;

    // Async-load A panel + first B tile. 4096 16B chunks each, 8 per thread.
    #pragma unroll
    for (int i = 0; i < 8; ++i) {
        int idx = tid + i * NTHREADS;
        int r = idx >> 5, c = idx & 31;
        cp16(As + r * KP + c * 8, g_fbf + (size_t)(bi * BM + r) * DIM + c * 8);
    }
    #pragma unroll
    for (int i = 0; i < 8; ++i) {
        int idx = tid + i * NTHREADS;
        int r = idx >> 5, c = idx & 31;
        cp16(Bbuf[0] + r * KP + c * 8, g_fbf + (size_t)(bj0 * BM + r) * DIM + c * 8);
    }
    cp_commit();

    int al = lane & 15;
    int acolo = (lane >> 4) * 8;
    int brow_off = lane & 7;
    int bcolo = ((lane >> 3) & 1) * 8;
    int g  = lane >> 2;
    int qd = (lane & 3) * 2;
    const float C10 = 14.426950408889634f;   // 10 * log2(e)

    float rowsum[4] = {0.f, 0.f, 0.f, 0.f};

    for (int t = 0; t < ntl; ++t) {
        cp_wait0();
        __syncthreads();

        if (t + 1 < ntl) {
            __nv_bfloat16* nb = Bbuf[(t + 1) & 1];
            const __nv_bfloat16* gsrc = g_fbf + (size_t)((bj0 + t + 1) * BM) * DIM;
            #pragma unroll
            for (int i = 0; i < 8; ++i) {
                int idx = tid + i * NTHREADS;
                int r = idx >> 5, c = idx & 31;
                cp16(nb + r * KP + c * 8, gsrc + (size_t)r * DIM + c * 8);
            }
        }
        cp_commit();

        const __nv_bfloat16* Bs = Bbuf[t & 1];
        int bj = bj0 + t;
        bool diag = (bj == bi);

        float cfr[2][4][4];
        #pragma unroll
        for (int mt = 0; mt < 2; ++mt)
            #pragma unroll
            for (int nt = 0; nt < 4; ++nt)
                #pragma unroll
                for (int e = 0; e < 4; ++e) cfr[mt][nt][e] = 0.f;

        #pragma unroll 4
        for (int kk = 0; kk < 16; ++kk) {
            int k0 = kk * 16;
            uint32_t afr[2][4], bfr[4][2];
            #pragma unroll
            for (int mt = 0; mt < 2; ++mt)
                ldsm_x4(afr[mt], As + (wm * 32 + mt * 16 + al) * KP + k0 + acolo);
            #pragma unroll
            for (int nt = 0; nt < 4; ++nt)
                ldsm_x2(bfr[nt], Bs + (wn * 32 + nt * 8 + brow_off) * KP + k0 + bcolo);
            #pragma unroll
            for (int mt = 0; mt < 2; ++mt)
                #pragma unroll
                for (int nt = 0; nt < 4; ++nt)
                    mma16816(cfr[mt][nt], afr[mt], bfr[nt]);
        }

        float colsum[4][2];
        #pragma unroll
        for (int nt = 0; nt < 4; ++nt) { colsum[nt][0] = 0.f; colsum[nt][1] = 0.f; }

        if (!diag) {
            // Off-diagonal: no masking needed (rows and cols never collide).
            #pragma unroll
            for (int mt = 0; mt < 2; ++mt) {
                #pragma unroll
                for (int nt = 0; nt < 4; ++nt) {
                    float* cc = cfr[mt][nt];
                    float e0 = ex2(fmaf(cc[0], C10, -C10));
                    float e1 = ex2(fmaf(cc[1], C10, -C10));
                    float e2 = ex2(fmaf(cc[2], C10, -C10));
                    float e3 = ex2(fmaf(cc[3], C10, -C10));
                    rowsum[mt * 2 + 0] += e0 + e1;
                    rowsum[mt * 2 + 1] += e2 + e3;
                    colsum[nt][0] += e0 + e2;
                    colsum[nt][1] += e1 + e3;
                }
            }
            #pragma unroll
            for (int nt = 0; nt < 4; ++nt) {
                float c0 = colsum[nt][0], c1 = colsum[nt][1];
                #pragma unroll
                for (int o = 4; o <= 16; o <<= 1) {
                    c0 += __shfl_xor_sync(0xffffffffu, c0, o);
                    c1 += __shfl_xor_sync(0xffffffffu, c1, o);
                }
                if (lane < 4) {
                    int col = bj * BM + wn * 32 + nt * 8 + lane * 2;
                    atomicAdd(&g_sumexp[col],     c0);
                    atomicAdd(&g_sumexp[col + 1], c1);
                }
            }
        } else {
            // Diagonal tile: mask r==c; col sums equal row sums (tile symmetric),
            // and this tile is counted once, so only row sums are accumulated.
            #pragma unroll
            for (int mt = 0; mt < 2; ++mt) {
                int r0 = wm * 32 + mt * 16 + g;
                #pragma unroll
                for (int nt = 0; nt < 4; ++nt) {
                    int c0i = wn * 32 + nt * 8 + qd;
                    float* cc = cfr[mt][nt];
                    float e0 = (c0i     != r0    ) ? ex2(fmaf(cc[0], C10, -C10)) : 0.f;
                    float e1 = (c0i + 1 != r0    ) ? ex2(fmaf(cc[1], C10, -C10)) : 0.f;
                    float e2 = (c0i     != r0 + 8) ? ex2(fmaf(cc[2], C10, -C10)) : 0.f;
                    float e3 = (c0i + 1 != r0 + 8) ? ex2(fmaf(cc[3], C10, -C10)) : 0.f;
                    rowsum[mt * 2 + 0] += e0 + e1;
                    rowsum[mt * 2 + 1] += e2 + e3;
                }
            }
        }
    }

    // Flush row sums.
    #pragma unroll
    for (int j = 0; j < 4; ++j) {
        rowsum[j] += __shfl_xor_sync(0xffffffffu, rowsum[j], 1);
        rowsum[j] += __shfl_xor_sync(0xffffffffu, rowsum[j], 2);
    }
    if ((lane & 3) == 0) {
        #pragma unroll
        for (int mt = 0; mt < 2; ++mt) {
            int r0 = bi * BM + wm * 32 + mt * 16 + g;
            atomicAdd(&g_sumexp[r0],     rowsum[mt * 2 + 0]);
            atomicAdd(&g_sumexp[r0 + 8], rowsum[mt * 2 + 1]);
        }
    }
}

// ---------------------------------------------------------------------------
__global__ void finalize_kernel(float* __restrict__ out) {
    int i = blockIdx.x * blockDim.x + threadIdx.x;
    float v = (10.f + __logf(g_sumexp[i]) - 10.f * g_pos[i]) * (1.0f / (float)NROWS);
    #pragma unroll
    for (int o = 16; o; o >>= 1) v += __shfl_xor_sync(0xffffffffu, v, o);
    if ((threadIdx.x & 31) == 0) atomicAdd(out, v);
}

extern "C" void kernel_launch(void* const* d_in, const int* in_sizes, int n_in,
                              void* d_out, int out_size) {
    const float* q = (const float*)d_in[0];
    const float* k = (const float*)d_in[1];
    float* out = (float*)d_out;

    cudaFuncSetAttribute(sim_kernel, cudaFuncAttributeMaxDynamicSharedMemorySize,
                         SMEM_BYTES);

    normalize_kernel<<<NROWS / 8, 256>>>(q, k);
    pos_kernel<<<HALFN / 8, 256>>>(q, k, out);
    sim_kernel<<<NCTAS, NTHREADS, SMEM_BYTES>>>();
    finalize_kernel<<<NROWS / 512, 512>>>(out);
}

// round 8
// speedup vs baseline: 2.2974x; 1.0247x over previous
#include <cuda_runtime.h>
#include <cuda_bf16.h>
#include <math.h>
#include <stdint.h>

// ContrastiveHead NT-Xent. Symmetric sim: upper-triangular 128x128 tiles.
// CTA = (row panel bi, <=8 bj tiles). 512 threads (16 warps, 4m x 4n).
// A resident, B double-buffered cp.async, paired ldsm_x4 for B.
// normalize+pos fused into one kernel; separate small finalize kernel.

#define NROWS 8192
#define HALFN 4096
#define DIM   256
#define BM    128
#define KP    264
#define NTILE 64
#define TSLICE 8
#define NCTAS 288
#define NTHREADS 512
#define SMEM_BYTES (3 * BM * KP * 2)

__device__ __nv_bfloat16 g_fbf[NROWS * DIM];
__device__ float g_pos[NROWS];
__device__ float g_sumexp[NROWS];

// ---------------------------------------------------------------------------
// Fused normalize + positives + accumulator/output zeroing.
// One warp per pair i: norms of q_i,k_i, dot, both normalized bf16 rows.
// ---------------------------------------------------------------------------
__global__ void normpos_kernel(const float* __restrict__ q,
                               const float* __restrict__ k,
                               float* __restrict__ out) {
    int gt = blockIdx.x * blockDim.x + threadIdx.x;
    if (gt == 0) out[0] = 0.0f;
    if (gt < NROWS) g_sumexp[gt] = 0.0f;
    int gw   = gt >> 5;            // pair index
    int lane = gt & 31;
    if (gw >= HALFN) return;

    const float4* q4 = (const float4*)(q + (size_t)gw * DIM);
    const float4* k4 = (const float4*)(k + (size_t)gw * DIM);
    float4 a0 = q4[lane*2], a1 = q4[lane*2+1];
    float4 b0 = k4[lane*2], b1 = k4[lane*2+1];
    float sq = a0.x*a0.x + a0.y*a0.y + a0.z*a0.z + a0.w*a0.w
             + a1.x*a1.x + a1.y*a1.y + a1.z*a1.z + a1.w*a1.w;
    float sk = b0.x*b0.x + b0.y*b0.y + b0.z*b0.z + b0.w*b0.w
             + b1.x*b1.x + b1.y*b1.y + b1.z*b1.z + b1.w*b1.w;
    float dp = a0.x*b0.x + a0.y*b0.y + a0.z*b0.z + a0.w*b0.w
             + a1.x*b1.x + a1.y*b1.y + a1.z*b1.z + a1.w*b1.w;
    #pragma unroll
    for (int o = 16; o; o >>= 1) {
        sq += __shfl_xor_sync(0xffffffffu, sq, o);
        sk += __shfl_xor_sync(0xffffffffu, sk, o);
        dp += __shfl_xor_sync(0xffffffffu, dp, o);
    }
    float nq = fmaxf(sqrtf(sq), 1e-12f);
    float nk = fmaxf(sqrtf(sk), 1e-12f);
    float sclq = 1.0f / nq;
    float sclk = 1.0f / nk;

    if (lane == 0) {
        float p = dp / (nq * nk);
        g_pos[gw]         = p;
        g_pos[gw + HALFN] = p;
    }

    __nv_bfloat162 h0 = __floats2bfloat162_rn(a0.x * sclq, a0.y * sclq);
    __nv_bfloat162 h1 = __floats2bfloat162_rn(a0.z * sclq, a0.w * sclq);
    __nv_bfloat162 h2 = __floats2bfloat162_rn(a1.x * sclq, a1.y * sclq);
    __nv_bfloat162 h3 = __floats2bfloat162_rn(a1.z * sclq, a1.w * sclq);
    uint4 oq;
    oq.x = *(const uint32_t*)&h0; oq.y = *(const uint32_t*)&h1;
    oq.z = *(const uint32_t*)&h2; oq.w = *(const uint32_t*)&h3;
    *(uint4*)(g_fbf + (size_t)gw * DIM + lane * 8) = oq;

    h0 = __floats2bfloat162_rn(b0.x * sclk, b0.y * sclk);
    h1 = __floats2bfloat162_rn(b0.z * sclk, b0.w * sclk);
    h2 = __floats2bfloat162_rn(b1.x * sclk, b1.y * sclk);
    h3 = __floats2bfloat162_rn(b1.z * sclk, b1.w * sclk);
    uint4 ok;
    ok.x = *(const uint32_t*)&h0; ok.y = *(const uint32_t*)&h1;
    ok.z = *(const uint32_t*)&h2; ok.w = *(const uint32_t*)&h3;
    *(uint4*)(g_fbf + (size_t)(gw + HALFN) * DIM + lane * 8) = ok;
}

// ---------------------------------------------------------------------------
__device__ __forceinline__ void ldsm_x4(uint32_t* r, const void* p) {
    uint32_t a = (uint32_t)__cvta_generic_to_shared(p);
    asm volatile("ldmatrix.sync.aligned.m8n8.x4.shared.b16 {%0,%1,%2,%3}, [%4];"
                 : "=r"(r[0]), "=r"(r[1]), "=r"(r[2]), "=r"(r[3]) : "r"(a));
}
__device__ __forceinline__ void mma16816(float* c, const uint32_t* a, const uint32_t* b) {
    asm volatile(
        "mma.sync.aligned.m16n8k16.row.col.f32.bf16.bf16.f32 "
        "{%0,%1,%2,%3}, {%4,%5,%6,%7}, {%8,%9}, {%0,%1,%2,%3};"
        : "+f"(c[0]), "+f"(c[1]), "+f"(c[2]), "+f"(c[3])
        : "r"(a[0]), "r"(a[1]), "r"(a[2]), "r"(a[3]), "r"(b[0]), "r"(b[1]));
}
__device__ __forceinline__ float ex2(float x) {
    float y; asm("ex2.approx.ftz.f32 %0, %1;" : "=f"(y) : "f"(x)); return y;
}
__device__ __forceinline__ void cp16(void* smem_dst, const void* gsrc) {
    uint32_t d = (uint32_t)__cvta_generic_to_shared(smem_dst);
    asm volatile("cp.async.cg.shared.global [%0], [%1], 16;" :: "r"(d), "l"(gsrc));
}
__device__ __forceinline__ void cp_commit() { asm volatile("cp.async.commit_group;"); }
__device__ __forceinline__ void cp_wait0()  { asm volatile("cp.async.wait_group 0;"); }

// ---------------------------------------------------------------------------
// Fused symmetric GEMM + exp. 512 threads = 16 warps (4m x 4n).
// Per warp: 2 m-tiles (m16) x 4 n-tiles (n8); B frags via paired ldsm_x4.
// ---------------------------------------------------------------------------
__global__ void __launch_bounds__(NTHREADS, 1) sim_kernel() {
    extern __shared__ __nv_bfloat16 sm[];
    __nv_bfloat16* As = sm;
    __nv_bfloat16* Bbuf[2] = { sm + BM * KP, sm + 2 * BM * KP };

    int tid = threadIdx.x;
    int lane = tid & 31;
    int w = tid >> 5;
    int wm = w >> 2;            // 0..3
    int wn = w & 3;             // 0..3

    int rem = blockIdx.x;
    int bi = 0;
    for (;;) {
        int s = (NTILE - bi + TSLICE - 1) / TSLICE;
        if (rem < s) break;
        rem -= s; ++bi;
    }
    int bj0 = bi + rem * TSLICE;
    int ntl = NTILE - bj0; if (ntl > TSLICE) ntl = TSLICE;

    #pragma unroll
    for (int i = 0; i < 8; ++i) {
        int idx = tid + i * NTHREADS;
        int r = idx >> 5, c = idx & 31;
        cp16(As + r * KP + c * 8, g_fbf + (size_t)(bi * BM + r) * DIM + c * 8);
    }
    #pragma unroll
    for (int i = 0; i < 8; ++i) {
        int idx = tid + i * NTHREADS;
        int r = idx >> 5, c = idx & 31;
        cp16(Bbuf[0] + r * KP + c * 8, g_fbf + (size_t)(bj0 * BM + r) * DIM + c * 8);
    }
    cp_commit();

    // ldmatrix addressing.
    int al = lane & 15;
    int acolo = (lane >> 4) * 8;
    int brow2 = ((lane >> 4) & 1) * 8 + (lane & 7);   // paired-B x4: row within 16
    int bcol2 = ((lane >> 3) & 1) * 8;                // paired-B x4: k-col half
    int g  = lane >> 2;
    int qd = (lane & 3) * 2;
    const float C10 = 14.426950408889634f;            // 10 * log2(e)

    float rowsum[4] = {0.f, 0.f, 0.f, 0.f};

    for (int t = 0; t < ntl; ++t) {
        cp_wait0();
        __syncthreads();

        if (t + 1 < ntl) {
            __nv_bfloat16* nb = Bbuf[(t + 1) & 1];
            const __nv_bfloat16* gsrc = g_fbf + (size_t)((bj0 + t + 1) * BM) * DIM;
            #pragma unroll
            for (int i = 0; i < 8; ++i) {
                int idx = tid + i * NTHREADS;
                int r = idx >> 5, c = idx & 31;
                cp16(nb + r * KP + c * 8, gsrc + (size_t)r * DIM + c * 8);
            }
        }
        cp_commit();

        const __nv_bfloat16* Bs = Bbuf[t & 1];
        int bj = bj0 + t;
        bool diag = (bj == bi);

        float cfr[2][4][4];
        #pragma unroll
        for (int mt = 0; mt < 2; ++mt)
            #pragma unroll
            for (int nt = 0; nt < 4; ++nt)
                #pragma unroll
                for (int e = 0; e < 4; ++e) cfr[mt][nt][e] = 0.f;

        #pragma unroll 4
        for (int kk = 0; kk < 16; ++kk) {
            int k0 = kk * 16;
            uint32_t afr[2][4], bfr[2][4];
            #pragma unroll
            for (int mt = 0; mt < 2; ++mt)
                ldsm_x4(afr[mt], As + (wm * 32 + mt * 16 + al) * KP + k0 + acolo);
            #pragma unroll
            for (int p = 0; p < 2; ++p)
                ldsm_x4(bfr[p], Bs + (wn * 32 + p * 16 + brow2) * KP + k0 + bcol2);
            #pragma unroll
            for (int mt = 0; mt < 2; ++mt)
                #pragma unroll
                for (int nt = 0; nt < 4; ++nt)
                    mma16816(cfr[mt][nt], afr[mt], &bfr[nt >> 1][(nt & 1) * 2]);
        }

        float colsum[4][2];
        #pragma unroll
        for (int nt = 0; nt < 4; ++nt) { colsum[nt][0] = 0.f; colsum[nt][1] = 0.f; }

        if (!diag) {
            #pragma unroll
            for (int mt = 0; mt < 2; ++mt) {
                #pragma unroll
                for (int nt = 0; nt < 4; ++nt) {
                    float* cc = cfr[mt][nt];
                    float e0 = ex2(fmaf(cc[0], C10, -C10));
                    float e1 = ex2(fmaf(cc[1], C10, -C10));
                    float e2 = ex2(fmaf(cc[2], C10, -C10));
                    float e3 = ex2(fmaf(cc[3], C10, -C10));
                    rowsum[mt * 2 + 0] += e0 + e1;
                    rowsum[mt * 2 + 1] += e2 + e3;
                    colsum[nt][0] += e0 + e2;
                    colsum[nt][1] += e1 + e3;
                }
            }
            #pragma unroll
            for (int nt = 0; nt < 4; ++nt) {
                float c0 = colsum[nt][0], c1 = colsum[nt][1];
                #pragma unroll
                for (int o = 4; o <= 16; o <<= 1) {
                    c0 += __shfl_xor_sync(0xffffffffu, c0, o);
                    c1 += __shfl_xor_sync(0xffffffffu, c1, o);
                }
                if (lane < 4) {
                    int col = bj * BM + wn * 32 + nt * 8 + lane * 2;
                    atomicAdd(&g_sumexp[col],     c0);
                    atomicAdd(&g_sumexp[col + 1], c1);
                }
            }
        } else {
            #pragma unroll
            for (int mt = 0; mt < 2; ++mt) {
                int r0 = wm * 32 + mt * 16 + g;
                #pragma unroll
                for (int nt = 0; nt < 4; ++nt) {
                    int c0i = wn * 32 + nt * 8 + qd;
                    float* cc = cfr[mt][nt];
                    float e0 = (c0i     != r0    ) ? ex2(fmaf(cc[0], C10, -C10)) : 0.f;
                    float e1 = (c0i + 1 != r0    ) ? ex2(fmaf(cc[1], C10, -C10)) : 0.f;
                    float e2 = (c0i     != r0 + 8) ? ex2(fmaf(cc[2], C10, -C10)) : 0.f;
                    float e3 = (c0i + 1 != r0 + 8) ? ex2(fmaf(cc[3], C10, -C10)) : 0.f;
                    rowsum[mt * 2 + 0] += e0 + e1;
                    rowsum[mt * 2 + 1] += e2 + e3;
                }
            }
        }
    }

    // Flush row sums.
    #pragma unroll
    for (int j = 0; j < 4; ++j) {
        rowsum[j] += __shfl_xor_sync(0xffffffffu, rowsum[j], 1);
        rowsum[j] += __shfl_xor_sync(0xffffffffu, rowsum[j], 2);
    }
    if ((lane & 3) == 0) {
        #pragma unroll
        for (int mt = 0; mt < 2; ++mt) {
            int r0 = bi * BM + wm * 32 + mt * 16 + g;
            atomicAdd(&g_sumexp[r0],     rowsum[mt * 2 + 0]);
            atomicAdd(&g_sumexp[r0 + 8], rowsum[mt * 2 + 1]);
        }
    }
}

// ---------------------------------------------------------------------------
__global__ void finalize_kernel(float* __restrict__ out) {
    int i = blockIdx.x * blockDim.x + threadIdx.x;
    float v = (10.f + __logf(g_sumexp[i]) - 10.f * g_pos[i]) * (1.0f / (float)NROWS);
    #pragma unroll
    for (int o = 16; o; o >>= 1) v += __shfl_xor_sync(0xffffffffu, v, o);
    if ((threadIdx.x & 31) == 0) atomicAdd(out, v);
}

extern "C" void kernel_launch(void* const* d_in, const int* in_sizes, int n_in,
                              void* d_out, int out_size) {
    const float* q = (const float*)d_in[0];
    const float* k = (const float*)d_in[1];
    float* out = (float*)d_out;

    cudaFuncSetAttribute(sim_kernel, cudaFuncAttributeMaxDynamicSharedMemorySize,
                         SMEM_BYTES);

    normpos_kernel<<<(HALFN * 32) / 256, 256>>>(q, k, out);
    sim_kernel<<<NCTAS, NTHREADS, SMEM_BYTES>>>();
    finalize_kernel<<<NROWS / 512, 512>>>(out);
}